// round 1
// baseline (speedup 1.0000x reference)
#include <cuda_runtime.h>
#include <cuda_bf16.h>

#define BB 2
#define LL 4096
#define DMODEL 512
#define NH 8
#define DHEAD 64

// Scratch (allocation-free rule: __device__ globals)
__device__ float g_Q[BB * NH * LL * DHEAD];
__device__ float g_K[BB * NH * LL * DHEAD];
__device__ float g_V[BB * NH * LL * DHEAD];
__device__ float g_O[BB * LL * DMODEL];

// ---------------------------------------------------------------------------
// 64x64 tiled fp32 GEMM, C[M,N] = A[M,512] @ B[512,N], N=512, KT=16.
// headed=1: write C into [B, H, L, 64] layout (head-split transpose on store).
// ---------------------------------------------------------------------------
__global__ __launch_bounds__(256) void gemm64(
    const float* __restrict__ A, const float* __restrict__ Bw,
    float* __restrict__ C, int headed)
{
    __shared__ float At[16][64];   // k-major: At[kk][m]
    __shared__ float Bs[16][64];   // Bs[kk][n]

    const int tid = threadIdx.x;
    const int tx = tid & 15, ty = tid >> 4;
    const int m0 = blockIdx.y * 64, n0 = blockIdx.x * 64;

    const int am  = tid & 63, akq = tid >> 6;   // A-loader: row am, k-quad akq
    const int brw = tid >> 4, bnq = tid & 15;   // B-loader: k-row brw, n-quad bnq

    const float* Ap = A + (size_t)(m0 + am) * DMODEL + akq * 4;
    const float* Bp = Bw + (size_t)brw * DMODEL + n0 + bnq * 4;

    float acc[4][4];
    #pragma unroll
    for (int i = 0; i < 4; i++)
        #pragma unroll
        for (int j = 0; j < 4; j++) acc[i][j] = 0.0f;

    for (int kt = 0; kt < DMODEL; kt += 16) {
        float4 av = *(const float4*)(Ap + kt);
        float4 bv = *(const float4*)(Bp + (size_t)kt * DMODEL);
        __syncthreads();
        At[akq * 4 + 0][am] = av.x;
        At[akq * 4 + 1][am] = av.y;
        At[akq * 4 + 2][am] = av.z;
        At[akq * 4 + 3][am] = av.w;
        *(float4*)&Bs[brw][bnq * 4] = bv;
        __syncthreads();
        #pragma unroll
        for (int kk = 0; kk < 16; kk++) {
            float4 a = *(const float4*)&At[kk][ty * 4];
            float4 b = *(const float4*)&Bs[kk][tx * 4];
            acc[0][0] += a.x * b.x; acc[0][1] += a.x * b.y; acc[0][2] += a.x * b.z; acc[0][3] += a.x * b.w;
            acc[1][0] += a.y * b.x; acc[1][1] += a.y * b.y; acc[1][2] += a.y * b.z; acc[1][3] += a.y * b.w;
            acc[2][0] += a.z * b.x; acc[2][1] += a.z * b.y; acc[2][2] += a.z * b.z; acc[2][3] += a.z * b.w;
            acc[3][0] += a.w * b.x; acc[3][1] += a.w * b.y; acc[3][2] += a.w * b.z; acc[3][3] += a.w * b.w;
        }
    }

    if (headed) {
        // m = b*L + l, n = h*64 + d. Tile has single b (m0 % 64 == 0, L % 64 == 0)
        // and single h (n-tile width == head width == 64, so h == blockIdx.x).
        const int b  = m0 >> 12;          // / 4096
        const int l0 = m0 & (LL - 1);
        const int h  = blockIdx.x;
        float* Cp = C + ((size_t)(b * NH + h) * LL) * DHEAD;
        #pragma unroll
        for (int i = 0; i < 4; i++) {
            float4 o = make_float4(acc[i][0], acc[i][1], acc[i][2], acc[i][3]);
            *(float4*)(Cp + (size_t)(l0 + ty * 4 + i) * DHEAD + tx * 4) = o;
        }
    } else {
        #pragma unroll
        for (int i = 0; i < 4; i++) {
            float4 o = make_float4(acc[i][0], acc[i][1], acc[i][2], acc[i][3]);
            *(float4*)(C + (size_t)(m0 + ty * 4 + i) * DMODEL + n0 + tx * 4) = o;
        }
    }
}

// ---------------------------------------------------------------------------
// Flash attention: grid (L/64, B*H). 64 queries per block, stream keys in
// 64-wide chunks. Q/K held d-major in smem (conflict-free float4 reads in the
// S loop), V k-major, P round-trips through smem for the P@V product.
// ---------------------------------------------------------------------------
__global__ __launch_bounds__(256) void attn_kernel(const int* __restrict__ mask)
{
    extern __shared__ float sm[];
    float* Qt   = sm;            // [64 d][64 q]
    float* Kt   = sm + 4096;     // [64 d][64 k]
    float* Vs   = sm + 8192;     // [64 k][64 d]
    float* Ps   = sm + 12288;    // [64 q][64 k]
    float* madd = sm + 16384;    // [64]

    const int tid = threadIdx.x;
    const int tx = tid & 15, ty = tid >> 4;
    const int q0 = blockIdx.x * 64;
    const int bh = blockIdx.y;
    const int b = bh >> 3, h = bh & 7;

    const float* Qg = g_Q + (size_t)bh * LL * DHEAD;
    const float* Kg = g_K + (size_t)bh * LL * DHEAD;
    const float* Vg = g_V + (size_t)bh * LL * DHEAD;
    const int* mg = mask + (size_t)b * LL;

    const int lk = tid & 63;     // row within 64-row tile
    const int lc = tid >> 6;     // base d-quad

    // Load Q tile transposed (d-major)
    #pragma unroll
    for (int t = 0; t < 4; t++) {
        int c = lc + t * 4;      // d-quad 0..15
        float4 v = *(const float4*)(Qg + (size_t)(q0 + lk) * DHEAD + c * 4);
        Qt[(c * 4 + 0) * 64 + lk] = v.x;
        Qt[(c * 4 + 1) * 64 + lk] = v.y;
        Qt[(c * 4 + 2) * 64 + lk] = v.z;
        Qt[(c * 4 + 3) * 64 + lk] = v.w;
    }

    float m_i[4], l_i[4], Oa[4][4];
    #pragma unroll
    for (int i = 0; i < 4; i++) {
        m_i[i] = -1e30f;
        l_i[i] = 0.0f;
        #pragma unroll
        for (int j = 0; j < 4; j++) Oa[i][j] = 0.0f;
    }

    for (int k0 = 0; k0 < LL; k0 += 64) {
        __syncthreads();  // previous iteration's readers of Kt/Vs/Ps are done

        // K tile transposed (d-major)
        #pragma unroll
        for (int t = 0; t < 4; t++) {
            int c = lc + t * 4;
            float4 kv = *(const float4*)(Kg + (size_t)(k0 + lk) * DHEAD + c * 4);
            Kt[(c * 4 + 0) * 64 + lk] = kv.x;
            Kt[(c * 4 + 1) * 64 + lk] = kv.y;
            Kt[(c * 4 + 2) * 64 + lk] = kv.z;
            Kt[(c * 4 + 3) * 64 + lk] = kv.w;
        }
        // V tile natural (k-major)
        #pragma unroll
        for (int t = 0; t < 4; t++) {
            int e = tid + t * 256;
            int vk = e >> 4, vd = e & 15;
            *(float4*)&Vs[vk * 64 + vd * 4] =
                *(const float4*)(Vg + (size_t)(k0 + vk) * DHEAD + vd * 4);
        }
        if (tid < 64) madd[tid] = mg[k0 + tid] ? 0.0f : -1e30f;
        __syncthreads();

        // S = Q K^T for this 64x64 block; thread owns rows ty*4+i, cols tx*4+j
        float S[4][4];
        #pragma unroll
        for (int i = 0; i < 4; i++)
            #pragma unroll
            for (int j = 0; j < 4; j++) S[i][j] = 0.0f;

        #pragma unroll 8
        for (int d = 0; d < 64; d++) {
            float4 qv = *(const float4*)&Qt[d * 64 + ty * 4];   // broadcast
            float4 kv = *(const float4*)&Kt[d * 64 + tx * 4];   // contiguous
            S[0][0] += qv.x * kv.x; S[0][1] += qv.x * kv.y; S[0][2] += qv.x * kv.z; S[0][3] += qv.x * kv.w;
            S[1][0] += qv.y * kv.x; S[1][1] += qv.y * kv.y; S[1][2] += qv.y * kv.z; S[1][3] += qv.y * kv.w;
            S[2][0] += qv.z * kv.x; S[2][1] += qv.z * kv.y; S[2][2] += qv.z * kv.z; S[2][3] += qv.z * kv.w;
            S[3][0] += qv.w * kv.x; S[3][1] += qv.w * kv.y; S[3][2] += qv.w * kv.z; S[3][3] += qv.w * kv.w;
        }

        const float scale = 0.125f;  // 1/sqrt(64)
        float ma0 = madd[tx * 4 + 0], ma1 = madd[tx * 4 + 1];
        float ma2 = madd[tx * 4 + 2], ma3 = madd[tx * 4 + 3];

        #pragma unroll
        for (int i = 0; i < 4; i++) {
            S[i][0] = S[i][0] * scale + ma0;
            S[i][1] = S[i][1] * scale + ma1;
            S[i][2] = S[i][2] * scale + ma2;
            S[i][3] = S[i][3] * scale + ma3;

            // row max across the 16 tx lanes (lanes [0..15] / [16..31] share ty)
            float r = fmaxf(fmaxf(S[i][0], S[i][1]), fmaxf(S[i][2], S[i][3]));
            r = fmaxf(r, __shfl_xor_sync(0xffffffffu, r, 1));
            r = fmaxf(r, __shfl_xor_sync(0xffffffffu, r, 2));
            r = fmaxf(r, __shfl_xor_sync(0xffffffffu, r, 4));
            r = fmaxf(r, __shfl_xor_sync(0xffffffffu, r, 8));

            float mn = fmaxf(m_i[i], r);
            float alpha = __expf(m_i[i] - mn);
            m_i[i] = mn;

            S[i][0] = __expf(S[i][0] - mn);
            S[i][1] = __expf(S[i][1] - mn);
            S[i][2] = __expf(S[i][2] - mn);
            S[i][3] = __expf(S[i][3] - mn);

            float rs = S[i][0] + S[i][1] + S[i][2] + S[i][3];
            rs += __shfl_xor_sync(0xffffffffu, rs, 1);
            rs += __shfl_xor_sync(0xffffffffu, rs, 2);
            rs += __shfl_xor_sync(0xffffffffu, rs, 4);
            rs += __shfl_xor_sync(0xffffffffu, rs, 8);

            l_i[i] = l_i[i] * alpha + rs;
            Oa[i][0] *= alpha; Oa[i][1] *= alpha; Oa[i][2] *= alpha; Oa[i][3] *= alpha;
        }

        // stage P in smem (q-major), then O += P @ V
        #pragma unroll
        for (int i = 0; i < 4; i++)
            *(float4*)&Ps[(ty * 4 + i) * 64 + tx * 4] =
                make_float4(S[i][0], S[i][1], S[i][2], S[i][3]);
        __syncthreads();

        #pragma unroll 8
        for (int kk = 0; kk < 64; kk++) {
            float4 vv = *(const float4*)&Vs[kk * 64 + tx * 4];  // contiguous
            float p0 = Ps[(ty * 4 + 0) * 64 + kk];              // broadcast
            float p1 = Ps[(ty * 4 + 1) * 64 + kk];
            float p2 = Ps[(ty * 4 + 2) * 64 + kk];
            float p3 = Ps[(ty * 4 + 3) * 64 + kk];
            Oa[0][0] += p0 * vv.x; Oa[0][1] += p0 * vv.y; Oa[0][2] += p0 * vv.z; Oa[0][3] += p0 * vv.w;
            Oa[1][0] += p1 * vv.x; Oa[1][1] += p1 * vv.y; Oa[1][2] += p1 * vv.z; Oa[1][3] += p1 * vv.w;
            Oa[2][0] += p2 * vv.x; Oa[2][1] += p2 * vv.y; Oa[2][2] += p2 * vv.z; Oa[2][3] += p2 * vv.w;
            Oa[3][0] += p3 * vv.x; Oa[3][1] += p3 * vv.y; Oa[3][2] += p3 * vv.z; Oa[3][3] += p3 * vv.w;
        }
    }

    // epilogue: normalize and write [B, L, H*64] (ready for output projection)
    #pragma unroll
    for (int i = 0; i < 4; i++) {
        float inv = 1.0f / l_i[i];
        float4 o = make_float4(Oa[i][0] * inv, Oa[i][1] * inv,
                               Oa[i][2] * inv, Oa[i][3] * inv);
        *(float4*)&g_O[((size_t)b * LL + q0 + ty * 4 + i) * DMODEL + h * DHEAD + tx * 4] = o;
    }
}

// ---------------------------------------------------------------------------
extern "C" void kernel_launch(void* const* d_in, const int* in_sizes, int n_in,
                              void* d_out, int out_size)
{
    const float* q    = (const float*)d_in[0];
    const float* k    = (const float*)d_in[1];
    const float* v    = (const float*)d_in[2];
    const int*   mask = (const int*)  d_in[3];
    const float* Wq   = (const float*)d_in[4];
    const float* Wk   = (const float*)d_in[5];
    const float* Wv   = (const float*)d_in[6];
    const float* Wo   = (const float*)d_in[7];
    float* out = (float*)d_out;

    void *pQ, *pK, *pV, *pO;
    cudaGetSymbolAddress(&pQ, g_Q);
    cudaGetSymbolAddress(&pK, g_K);
    cudaGetSymbolAddress(&pV, g_V);
    cudaGetSymbolAddress(&pO, g_O);

    const int attn_smem = (4 * 4096 + 64) * sizeof(float);  // 65792 B
    cudaFuncSetAttribute(attn_kernel,
                         cudaFuncAttributeMaxDynamicSharedMemorySize, attn_smem);

    dim3 blk(256);
    dim3 gproj(DMODEL / 64, (BB * LL) / 64);   // (8, 128)

    gemm64<<<gproj, blk>>>(q, Wq, (float*)pQ, 1);
    gemm64<<<gproj, blk>>>(k, Wk, (float*)pK, 1);
    gemm64<<<gproj, blk>>>(v, Wv, (float*)pV, 1);
    attn_kernel<<<dim3(LL / 64, BB * NH), blk, attn_smem>>>(mask);
    gemm64<<<gproj, blk>>>((const float*)pO, Wo, out, 0);
}

// round 3
// speedup vs baseline: 3.3238x; 3.3238x over previous
#include <cuda_runtime.h>
#include <cstdint>

#define BB 2
#define LL 4096
#define DMODEL 512
#define NH 8
#define DHEAD 64

// Scratch (allocation-free rule: __device__ globals)
__device__ float g_Q[BB * NH * LL * DHEAD];
__device__ float g_K[BB * NH * LL * DHEAD];
__device__ float g_V[BB * NH * LL * DHEAD];
__device__ float g_O[BB * LL * DMODEL];

__device__ __forceinline__ uint32_t f2tf(float x) {
    uint32_t r;
    asm("cvt.rna.tf32.f32 %0, %1;" : "=r"(r) : "f"(x));
    return r;
}

// D += A(16x8) * B(8x8), tf32 inputs, fp32 accumulate
__device__ __forceinline__ void mma8(float* c, const uint32_t* a, const uint32_t* b) {
    asm volatile(
        "mma.sync.aligned.m16n8k8.row.col.f32.tf32.tf32.f32 "
        "{%0,%1,%2,%3}, {%4,%5,%6,%7}, {%8,%9}, {%0,%1,%2,%3};"
        : "+f"(c[0]), "+f"(c[1]), "+f"(c[2]), "+f"(c[3])
        : "r"(a[0]), "r"(a[1]), "r"(a[2]), "r"(a[3]), "r"(b[0]), "r"(b[1]));
}

// ---------------------------------------------------------------------------
// tf32 GEMM: C[M,N] = A[M,512] @ B[512,N], tile 128x128, 256 threads.
// headed=1: scatter C into [B, H, L, 64] head-split layout.
// ---------------------------------------------------------------------------
#define GP_A 36
#define GP_B 136

__global__ __launch_bounds__(256, 2) void gemm_tf32(
    const float* __restrict__ A, const float* __restrict__ Bw,
    float* __restrict__ C, int headed)
{
    __shared__ uint32_t As[128 * GP_A];   // [m][k-chunk of 32], pad 36
    __shared__ uint32_t Bs[32 * GP_B];    // [k][n 128], pad 136

    const int tid = threadIdx.x;
    const int lane = tid & 31;
    const int wid = tid >> 5;
    const int g = lane >> 2, tig = lane & 3;
    const int wm = (wid & 3) * 32;    // warp m offset (4 warps over 128)
    const int wn = (wid >> 2) * 64;   // warp n offset (2 warps over 128)
    const int m0 = blockIdx.y * 128, n0 = blockIdx.x * 128;

    float acc[2][8][4];
    #pragma unroll
    for (int mt = 0; mt < 2; mt++)
        #pragma unroll
        for (int j = 0; j < 8; j++)
            #pragma unroll
            for (int r = 0; r < 4; r++) acc[mt][j][r] = 0.0f;

    for (int kt = 0; kt < DMODEL; kt += 32) {
        __syncthreads();
        #pragma unroll
        for (int i = 0; i < 4; i++) {
            int idx = tid + i * 256;
            int r = idx >> 3, c = (idx & 7) * 4;
            float4 v = *(const float4*)(A + (size_t)(m0 + r) * DMODEL + kt + c);
            uint32_t* p = &As[r * GP_A + c];
            p[0] = f2tf(v.x); p[1] = f2tf(v.y); p[2] = f2tf(v.z); p[3] = f2tf(v.w);
        }
        #pragma unroll
        for (int i = 0; i < 4; i++) {
            int idx = tid + i * 256;
            int r = idx >> 5, c = (idx & 31) * 4;
            float4 v = *(const float4*)(Bw + (size_t)(kt + r) * DMODEL + n0 + c);
            uint32_t* p = &Bs[r * GP_B + c];
            p[0] = f2tf(v.x); p[1] = f2tf(v.y); p[2] = f2tf(v.z); p[3] = f2tf(v.w);
        }
        __syncthreads();

        #pragma unroll
        for (int kk = 0; kk < 4; kk++) {
            uint32_t af[2][4], bf[8][2];
            #pragma unroll
            for (int mt = 0; mt < 2; mt++) {
                int r = wm + mt * 16;
                af[mt][0] = As[(r + g) * GP_A + kk * 8 + tig];
                af[mt][1] = As[(r + g + 8) * GP_A + kk * 8 + tig];
                af[mt][2] = As[(r + g) * GP_A + kk * 8 + tig + 4];
                af[mt][3] = As[(r + g + 8) * GP_A + kk * 8 + tig + 4];
            }
            #pragma unroll
            for (int j = 0; j < 8; j++) {
                bf[j][0] = Bs[(kk * 8 + tig) * GP_B + wn + j * 8 + g];
                bf[j][1] = Bs[(kk * 8 + tig + 4) * GP_B + wn + j * 8 + g];
            }
            #pragma unroll
            for (int mt = 0; mt < 2; mt++)
                #pragma unroll
                for (int j = 0; j < 8; j++)
                    mma8(acc[mt][j], af[mt], bf[j]);
        }
    }

    #pragma unroll
    for (int mt = 0; mt < 2; mt++) {
        int m_lo = m0 + wm + mt * 16 + g;
        int m_hi = m_lo + 8;
        #pragma unroll
        for (int j = 0; j < 8; j++) {
            int n = n0 + wn + j * 8 + 2 * tig;
            float2 vlo = make_float2(acc[mt][j][0], acc[mt][j][1]);
            float2 vhi = make_float2(acc[mt][j][2], acc[mt][j][3]);
            if (headed) {
                int h = n >> 6, d = n & 63;
                int b_lo = m_lo >> 12, l_lo = m_lo & (LL - 1);
                int b_hi = m_hi >> 12, l_hi = m_hi & (LL - 1);
                *(float2*)&C[(((size_t)(b_lo * NH + h)) * LL + l_lo) * DHEAD + d] = vlo;
                *(float2*)&C[(((size_t)(b_hi * NH + h)) * LL + l_hi) * DHEAD + d] = vhi;
            } else {
                *(float2*)&C[(size_t)m_lo * DMODEL + n] = vlo;
                *(float2*)&C[(size_t)m_hi * DMODEL + n] = vhi;
            }
        }
    }
}

// ---------------------------------------------------------------------------
// tf32 flash attention: grid (L/64, B*H), 128 threads (4 warps, 16 q each).
// Row stride must exceed tile width 64: KP=68 (banks 4g+tig, conflict-free),
// VP=72 (banks 8tig+g, conflict-free). Q staged through Ks, then registers.
// ---------------------------------------------------------------------------
#define KP 68
#define VP 72

__global__ __launch_bounds__(128, 3) void attn_tf32(const int* __restrict__ mask)
{
    __shared__ uint32_t Ks[64 * KP];
    __shared__ uint32_t Vs[64 * VP];
    __shared__ float madd[64];

    const int tid = threadIdx.x;
    const int lane = tid & 31;
    const int wid = tid >> 5;           // 0..3, one warp per SMSP
    const int g = lane >> 2, tig = lane & 3;
    const int bl = lane & 28;           // group base lane (4*g)
    const int lo = tig >> 1, sel = tig & 1;

    const int q0 = blockIdx.x * 64;
    const int bh = blockIdx.y;
    const int b = bh >> 3, h = bh & 7;

    const float* Qg = g_Q + (size_t)bh * LL * DHEAD;
    const float* Kg = g_K + (size_t)bh * LL * DHEAD;
    const float* Vg = g_V + (size_t)bh * LL * DHEAD;
    const int* mg = mask + (size_t)b * LL;

    // Prologue: stage Q tile through the Ks buffer, pull fragments to regs
    #pragma unroll
    for (int i = 0; i < 8; i++) {
        int idx = tid + i * 128;
        int r = idx >> 4, c = (idx & 15) * 4;
        float4 v = *(const float4*)(Qg + (size_t)(q0 + r) * DHEAD + c);
        uint32_t* p = &Ks[r * KP + c];
        p[0] = f2tf(v.x); p[1] = f2tf(v.y); p[2] = f2tf(v.z); p[3] = f2tf(v.w);
    }
    __syncthreads();

    uint32_t qa[8][4];
    const int qr = wid * 16;
    #pragma unroll
    for (int kk = 0; kk < 8; kk++) {
        qa[kk][0] = Ks[(qr + g) * KP + kk * 8 + tig];
        qa[kk][1] = Ks[(qr + g + 8) * KP + kk * 8 + tig];
        qa[kk][2] = Ks[(qr + g) * KP + kk * 8 + tig + 4];
        qa[kk][3] = Ks[(qr + g + 8) * KP + kk * 8 + tig + 4];
    }

    float Oacc[8][4];
    #pragma unroll
    for (int j = 0; j < 8; j++)
        #pragma unroll
        for (int r = 0; r < 4; r++) Oacc[j][r] = 0.0f;
    float m_lo = -1e30f, m_hi = -1e30f, l_lo = 0.0f, l_hi = 0.0f;

    for (int k0 = 0; k0 < LL; k0 += 64) {
        __syncthreads();   // prior chunk's readers (and the qa prologue) done
        #pragma unroll
        for (int i = 0; i < 8; i++) {
            int idx = tid + i * 128;
            int r = idx >> 4, c = (idx & 15) * 4;
            float4 kv = *(const float4*)(Kg + (size_t)(k0 + r) * DHEAD + c);
            uint32_t* pk = &Ks[r * KP + c];
            pk[0] = f2tf(kv.x); pk[1] = f2tf(kv.y); pk[2] = f2tf(kv.z); pk[3] = f2tf(kv.w);
            float4 vv = *(const float4*)(Vg + (size_t)(k0 + r) * DHEAD + c);
            uint32_t* pv = &Vs[r * VP + c];
            pv[0] = f2tf(vv.x); pv[1] = f2tf(vv.y); pv[2] = f2tf(vv.z); pv[3] = f2tf(vv.w);
        }
        if (tid < 64) madd[tid] = mg[k0 + tid] ? 0.0f : -1e30f;
        __syncthreads();

        // S = Q @ K^T : 8 key-tiles x 8 k-steps
        float Sc[8][4];
        #pragma unroll
        for (int j = 0; j < 8; j++)
            #pragma unroll
            for (int r = 0; r < 4; r++) Sc[j][r] = 0.0f;

        #pragma unroll
        for (int kk = 0; kk < 8; kk++) {
            #pragma unroll
            for (int j = 0; j < 8; j++) {
                uint32_t bf[2];
                bf[0] = Ks[(j * 8 + g) * KP + kk * 8 + tig];
                bf[1] = Ks[(j * 8 + g) * KP + kk * 8 + tig + 4];
                mma8(Sc[j], qa[kk], bf);
            }
        }

        // online softmax
        const float scale = 0.125f;
        float rmax_lo = -1e30f, rmax_hi = -1e30f;
        #pragma unroll
        for (int j = 0; j < 8; j++) {
            float ma0 = madd[j * 8 + 2 * tig];
            float ma1 = madd[j * 8 + 2 * tig + 1];
            Sc[j][0] = Sc[j][0] * scale + ma0;
            Sc[j][1] = Sc[j][1] * scale + ma1;
            Sc[j][2] = Sc[j][2] * scale + ma0;
            Sc[j][3] = Sc[j][3] * scale + ma1;
            rmax_lo = fmaxf(rmax_lo, fmaxf(Sc[j][0], Sc[j][1]));
            rmax_hi = fmaxf(rmax_hi, fmaxf(Sc[j][2], Sc[j][3]));
        }
        rmax_lo = fmaxf(rmax_lo, __shfl_xor_sync(0xffffffffu, rmax_lo, 1));
        rmax_lo = fmaxf(rmax_lo, __shfl_xor_sync(0xffffffffu, rmax_lo, 2));
        rmax_hi = fmaxf(rmax_hi, __shfl_xor_sync(0xffffffffu, rmax_hi, 1));
        rmax_hi = fmaxf(rmax_hi, __shfl_xor_sync(0xffffffffu, rmax_hi, 2));

        float mn_lo = fmaxf(m_lo, rmax_lo), mn_hi = fmaxf(m_hi, rmax_hi);
        float al = __expf(m_lo - mn_lo), ah = __expf(m_hi - mn_hi);
        m_lo = mn_lo; m_hi = mn_hi;

        float rs_lo = 0.0f, rs_hi = 0.0f;
        uint32_t pa[8][4];
        #pragma unroll
        for (int j = 0; j < 8; j++) {
            float p0 = __expf(Sc[j][0] - mn_lo);
            float p1 = __expf(Sc[j][1] - mn_lo);
            float p2 = __expf(Sc[j][2] - mn_hi);
            float p3 = __expf(Sc[j][3] - mn_hi);
            rs_lo += p0 + p1;
            rs_hi += p2 + p3;
            // C-layout (cols 2tig,2tig+1) -> A-layout (cols tig, tig+4) via shfl
            float t00 = __shfl_sync(0xffffffffu, p0, bl | lo);
            float t01 = __shfl_sync(0xffffffffu, p1, bl | lo);
            float t20 = __shfl_sync(0xffffffffu, p0, bl | lo | 2);
            float t21 = __shfl_sync(0xffffffffu, p1, bl | lo | 2);
            float t10 = __shfl_sync(0xffffffffu, p2, bl | lo);
            float t11 = __shfl_sync(0xffffffffu, p3, bl | lo);
            float t30 = __shfl_sync(0xffffffffu, p2, bl | lo | 2);
            float t31 = __shfl_sync(0xffffffffu, p3, bl | lo | 2);
            pa[j][0] = f2tf(sel ? t01 : t00);
            pa[j][1] = f2tf(sel ? t11 : t10);
            pa[j][2] = f2tf(sel ? t21 : t20);
            pa[j][3] = f2tf(sel ? t31 : t30);
        }
        rs_lo += __shfl_xor_sync(0xffffffffu, rs_lo, 1);
        rs_lo += __shfl_xor_sync(0xffffffffu, rs_lo, 2);
        rs_hi += __shfl_xor_sync(0xffffffffu, rs_hi, 1);
        rs_hi += __shfl_xor_sync(0xffffffffu, rs_hi, 2);

        l_lo = l_lo * al + rs_lo;
        l_hi = l_hi * ah + rs_hi;
        #pragma unroll
        for (int j = 0; j < 8; j++) {
            Oacc[j][0] *= al; Oacc[j][1] *= al;
            Oacc[j][2] *= ah; Oacc[j][3] *= ah;
        }

        // O += P @ V
        #pragma unroll
        for (int kk = 0; kk < 8; kk++) {
            #pragma unroll
            for (int j = 0; j < 8; j++) {
                uint32_t bf[2];
                bf[0] = Vs[(kk * 8 + tig) * VP + j * 8 + g];
                bf[1] = Vs[(kk * 8 + tig + 4) * VP + j * 8 + g];
                mma8(Oacc[j], pa[kk], bf);
            }
        }
    }

    // epilogue: normalize, write [B, L, H*64]
    float inv_lo = 1.0f / l_lo, inv_hi = 1.0f / l_hi;
    int row_lo = q0 + wid * 16 + g;
    int row_hi = row_lo + 8;
    #pragma unroll
    for (int j = 0; j < 8; j++) {
        int col = h * DHEAD + j * 8 + 2 * tig;
        *(float2*)&g_O[((size_t)b * LL + row_lo) * DMODEL + col] =
            make_float2(Oacc[j][0] * inv_lo, Oacc[j][1] * inv_lo);
        *(float2*)&g_O[((size_t)b * LL + row_hi) * DMODEL + col] =
            make_float2(Oacc[j][2] * inv_hi, Oacc[j][3] * inv_hi);
    }
}

// ---------------------------------------------------------------------------
extern "C" void kernel_launch(void* const* d_in, const int* in_sizes, int n_in,
                              void* d_out, int out_size)
{
    const float* q    = (const float*)d_in[0];
    const float* k    = (const float*)d_in[1];
    const float* v    = (const float*)d_in[2];
    const int*   mask = (const int*)  d_in[3];
    const float* Wq   = (const float*)d_in[4];
    const float* Wk   = (const float*)d_in[5];
    const float* Wv   = (const float*)d_in[6];
    const float* Wo   = (const float*)d_in[7];
    float* out = (float*)d_out;

    void *pQ, *pK, *pV, *pO;
    cudaGetSymbolAddress(&pQ, g_Q);
    cudaGetSymbolAddress(&pK, g_K);
    cudaGetSymbolAddress(&pV, g_V);
    cudaGetSymbolAddress(&pO, g_O);

    dim3 blk(256);
    dim3 gproj(DMODEL / 128, (BB * LL) / 128);   // (4, 64)

    gemm_tf32<<<gproj, blk>>>(q, Wq, (float*)pQ, 1);
    gemm_tf32<<<gproj, blk>>>(k, Wk, (float*)pK, 1);
    gemm_tf32<<<gproj, blk>>>(v, Wv, (float*)pV, 1);
    attn_tf32<<<dim3(LL / 64, BB * NH), 128>>>(mask);
    gemm_tf32<<<gproj, blk>>>((const float*)pO, Wo, out, 0);
}